// round 17
// baseline (speedup 1.0000x reference)
#include <cuda_runtime.h>
#include <cuda_bf16.h>
#include <cstdint>

#define SS   64
#define BB   32
#define HID  16
#define EMB  32
#define VV   50257
#define VPAD 50304          // 393 * 128
#define NT_G (VPAD/8)       // 6288 global n8-tiles
#define MT_G (2048/16)      // 128 global m16-tiles
#define SB   (SS*BB)        // 2048
#define GG   64
#define COMB (EMB+HID)      // 48

#define PREP_THREADS (NT_G*32)              // 201216
#define PREP_BLKS ((PREP_THREADS+255)/256)  // 786
#define PRE_BLKS  (SB*GG/256)               // 512

// scratch (no allocations allowed)
__device__ float g_X[SB*GG];            // input-part of gates
__device__ uint4 g_HtP4[MT_G*32*2];     // A fragments: [m16tile][lane][ks] bf16x8
__device__ uint4 g_WtP4[NT_G*32];       // B fragments: [n8tile][lane] bf16x8 (both ks)
__device__ float g_bpad[VPAD];          // bias, padded with -100 (exp -> 0)
__device__ float g_sumexp[SB];

// ---------------------------------------------------------------------------
__device__ __forceinline__ void mma_bf16(float d[4], const uint32_t a0,
                                         const uint32_t a1, const uint32_t a2,
                                         const uint32_t a3, const uint32_t b0,
                                         const uint32_t b1) {
    asm volatile(
        "mma.sync.aligned.m16n8k16.row.col.f32.bf16.bf16.f32 "
        "{%0,%1,%2,%3}, {%4,%5,%6,%7}, {%8,%9}, {%0,%1,%2,%3};"
        : "+f"(d[0]), "+f"(d[1]), "+f"(d[2]), "+f"(d[3])
        : "r"(a0), "r"(a1), "r"(a2), "r"(a3), "r"(b0), "r"(b1));
}

// A element (m,k) -> bf16 slot in g_HtP4 (k_recur's tiny scatter)
__device__ __forceinline__ int a_frag_addr(int m, int k) {
    int mt_g = m >> 4, r = m & 15;
    int gq = r & 7, mh = r >> 3;
    int ks = k >> 4, kk = k & 15;
    int tg = (kk >> 1) & 3, kh = kk >> 3, pr = kk & 1;
    int lane = gq * 4 + tg;
    int w = kh * 2 + mh;
    return (((mt_g * 32 + lane) * 2 + ks) * 4 + w) * 2 + pr;
}

// ---------------------------------------------------------------------------
// K0 (fused): range A: Who -> coalesced bf16 B-fragments + padded bias +
// sumexp zero. range B: X[sb][g] = b_gate + emb[idx[sb]] . W_gate[h][0:32].
__global__ void k_prep(const float* __restrict__ Who, const float* __restrict__ bho,
                       const int* __restrict__ idx, const float* __restrict__ emb,
                       const float* __restrict__ Wf, const float* __restrict__ bf,
                       const float* __restrict__ Wi, const float* __restrict__ bi,
                       const float* __restrict__ Wc, const float* __restrict__ bc,
                       const float* __restrict__ Wo, const float* __restrict__ bo) {
    if (blockIdx.x < PREP_BLKS) {
        int t = blockIdx.x * 256 + threadIdx.x;
        if (t < SB) g_sumexp[t] = 0.f;
        if (t < VPAD) g_bpad[t] = (t < VV) ? bho[t] : -100.f;
        if (t >= PREP_THREADS) return;
        int lane = t & 31, nt_g = t >> 5;
        int gq = lane >> 2, tg = lane & 3;
        int v = nt_g * 8 + gq;
        uint32_t wds[4] = {0u, 0u, 0u, 0u};
        if (v < VV) {
            const float* row = Who + v * 32;
#pragma unroll
            for (int w = 0; w < 4; w++) {
                int k0 = 16 * (w >> 1) + 8 * (w & 1) + tg * 2;
                float2 f = *(const float2*)&row[k0];
                __nv_bfloat162 h2 = __floats2bfloat162_rn(f.x, f.y);
                wds[w] = *(uint32_t*)&h2;
            }
        }
        g_WtP4[t] = make_uint4(wds[0], wds[1], wds[2], wds[3]);
    } else {
        int t = (blockIdx.x - PREP_BLKS) * 256 + threadIdx.x;   // < SB*GG
        int g    = t & 63;
        int sb   = t >> 6;
        int gate = g >> 4;
        int hh   = g & 15;
        const float* W  = gate == 0 ? Wf : gate == 1 ? Wi : gate == 2 ? Wc : Wo;
        const float* bb = gate == 0 ? bf : gate == 1 ? bi : gate == 2 ? bc : bo;
        const float* e  = emb + (long long)idx[sb] * EMB;
        const float* w  = W + hh * COMB;
        float acc = bb[hh];
#pragma unroll
        for (int k = 0; k < EMB; k++) acc = fmaf(e[k], w[k], acc);
        g_X[t] = acc;
    }
}

// ---------------------------------------------------------------------------
// K2: bidirectional recurrence, one warp per (direction, batch); X prefetched.
__global__ void k_recur(const float* __restrict__ Wf, const float* __restrict__ Wi,
                        const float* __restrict__ Wc, const float* __restrict__ Wo,
                        const float* __restrict__ h0, const float* __restrict__ C0) {
    int b   = blockIdx.x & 31;
    int dir = blockIdx.x >> 5;
    int t   = threadIdx.x;          // 0..31
    int hh  = t & 15;
    const float* W0 = (t < 16) ? Wf : Wi;
    const float* W1 = (t < 16) ? Wc : Wo;
    float w0[HID], w1[HID];
#pragma unroll
    for (int k = 0; k < HID; k++) {
        w0[k] = W0[hh * COMB + EMB + k];
        w1[k] = W1[hh * COMB + EMB + k];
    }
    float h = h0[hh];
    float C = C0[hh];

    int s0  = dir ? (SS - 1) : 0;
    int sb0 = s0 * BB + b;
    float nx0 = g_X[sb0 * 64 + t];
    float nx1 = g_X[sb0 * 64 + 32 + t];

    for (int step = 0; step < SS; step++) {
        int s  = dir ? (SS - 1 - step) : step;
        int sb = s * BB + b;
        float acc0 = nx0;
        float acc1 = nx1;
        if (step + 1 < SS) {
            int sn  = dir ? (SS - 2 - step) : (step + 1);
            int sbn = sn * BB + b;
            nx0 = g_X[sbn * 64 + t];
            nx1 = g_X[sbn * 64 + 32 + t];
        }
        if (t < 16)
            ((__nv_bfloat16*)g_HtP4)[a_frag_addr(sb, dir * 16 + hh)] =
                __float2bfloat16_rn(h);
#pragma unroll
        for (int k = 0; k < HID; k++) {
            float hk = __shfl_sync(0xffffffffu, h, k);
            acc0 = fmaf(hk, w0[k], acc0);
            acc1 = fmaf(hk, w1[k], acc1);
        }
        float a0 = 1.f / (1.f + __expf(-acc0));                          // f or i
        float a1 = (t < 16) ? tanhf(acc1) : 1.f / (1.f + __expf(-acc1)); // C~ or o
        float iv = __shfl_down_sync(0xffffffffu, a0, 16);
        float ov = __shfl_down_sync(0xffffffffu, a1, 16);
        if (t < 16) {
            C = a0 * C + iv * a1;
            h = ov * tanhf(C);
        }
    }
}

// ---------------------------------------------------------------------------
// GEMM kernels: block 256 thr = 8 warps (4m x 2n), tile 128sb x 128v.
// nt-outer restructure: only one B-fragment + 8 accumulators live at a time
// -> ~55 regs -> 4 blocks/SM. A fragments preloaded (reused across all nt).
#define N_BLK 128
#define M_BLK 128

// K3a: sum(exp(logit)) per row. Padded bias (-100) makes it guard-free.
__global__ __launch_bounds__(256)
void k_sumexp(int dummy) {
    __shared__ float sume[M_BLK];

    int tid   = threadIdx.x;
    int lane  = tid & 31;
    int wid   = tid >> 5;
    int warpM = wid & 3;
    int warpN = wid >> 2;
    int gq    = lane >> 2;
    int tg    = lane & 3;

    int vbase  = blockIdx.x * N_BLK;
    int sbbase = blockIdx.y * M_BLK;

    if (tid < M_BLK) sume[tid] = 0.f;

    uint4 Av[2][2];
#pragma unroll
    for (int mt = 0; mt < 2; mt++) {
        int mt_g = (sbbase >> 4) + warpM * 2 + mt;
        Av[mt][0] = g_HtP4[(mt_g * 32 + lane) * 2 + 0];
        Av[mt][1] = g_HtP4[(mt_g * 32 + lane) * 2 + 1];
    }

    float rs[4] = {0.f, 0.f, 0.f, 0.f};
#pragma unroll
    for (int nt = 0; nt < 8; nt++) {
        uint4 Bv = g_WtP4[((vbase >> 3) + warpN * 8 + nt) * 32 + lane];
        int v0 = vbase + warpN * 64 + nt * 8 + 2 * tg;
        float2 b01 = *(const float2*)&g_bpad[v0];
#pragma unroll
        for (int mt = 0; mt < 2; mt++) {
            float acc[4] = {b01.x, b01.y, b01.x, b01.y};
            mma_bf16(acc, Av[mt][0].x, Av[mt][0].y, Av[mt][0].z, Av[mt][0].w,
                     Bv.x, Bv.y);
            mma_bf16(acc, Av[mt][1].x, Av[mt][1].y, Av[mt][1].z, Av[mt][1].w,
                     Bv.z, Bv.w);
            rs[mt * 2 + 0] += __expf(acc[0]) + __expf(acc[1]);
            rs[mt * 2 + 1] += __expf(acc[2]) + __expf(acc[3]);
        }
    }

    __syncthreads();
#pragma unroll
    for (int j = 0; j < 4; j++) {
        rs[j] += __shfl_xor_sync(0xffffffffu, rs[j], 1);
        rs[j] += __shfl_xor_sync(0xffffffffu, rs[j], 2);
    }
    if (tg == 0) {
        // rows: warpM*32 + mt*16 + ch*8 + gq  (j = mt*2+ch)
        atomicAdd(&sume[warpM * 32 + 0 * 16 + 0 * 8 + gq], rs[0]);
        atomicAdd(&sume[warpM * 32 + 0 * 16 + 1 * 8 + gq], rs[1]);
        atomicAdd(&sume[warpM * 32 + 1 * 16 + 0 * 8 + gq], rs[2]);
        atomicAdd(&sume[warpM * 32 + 1 * 16 + 1 * 8 + gq], rs[3]);
    }
    __syncthreads();
    if (tid < M_BLK) atomicAdd(&g_sumexp[sbbase + tid], sume[tid]);
}

// K3b: recompute logits, write logit - log(sumexp). Tail guards only in the
// last v-block (uniform branch).
__global__ __launch_bounds__(256)
void k_write(float* __restrict__ out) {
    int tid   = threadIdx.x;
    int lane  = tid & 31;
    int wid   = tid >> 5;
    int warpM = wid & 3;
    int warpN = wid >> 2;
    int gq    = lane >> 2;
    int tg    = lane & 3;

    int vbase  = blockIdx.x * N_BLK;
    int sbbase = blockIdx.y * M_BLK;

    uint4 Av[2][2];
#pragma unroll
    for (int mt = 0; mt < 2; mt++) {
        int mt_g = (sbbase >> 4) + warpM * 2 + mt;
        Av[mt][0] = g_HtP4[(mt_g * 32 + lane) * 2 + 0];
        Av[mt][1] = g_HtP4[(mt_g * 32 + lane) * 2 + 1];
    }

    // per-thread rows: [mt][ch] = warpM*32 + mt*16 + ch*8 + gq
    float lse[2][2];
    long long rbase[2][2];
#pragma unroll
    for (int mt = 0; mt < 2; mt++)
#pragma unroll
        for (int ch = 0; ch < 2; ch++) {
            int rloc = warpM * 32 + mt * 16 + ch * 8 + gq;
            lse[mt][ch] = __logf(g_sumexp[sbbase + rloc]);
            rbase[mt][ch] = (long long)(sbbase + rloc) * VV;
        }

    bool full = (vbase + N_BLK <= VV);   // uniform across block

#pragma unroll
    for (int nt = 0; nt < 8; nt++) {
        uint4 Bv = g_WtP4[((vbase >> 3) + warpN * 8 + nt) * 32 + lane];
        int v0 = vbase + warpN * 64 + nt * 8 + 2 * tg;
        float2 b01 = *(const float2*)&g_bpad[v0];
#pragma unroll
        for (int mt = 0; mt < 2; mt++) {
            float acc[4] = {b01.x, b01.y, b01.x, b01.y};
            mma_bf16(acc, Av[mt][0].x, Av[mt][0].y, Av[mt][0].z, Av[mt][0].w,
                     Bv.x, Bv.y);
            mma_bf16(acc, Av[mt][1].x, Av[mt][1].y, Av[mt][1].z, Av[mt][1].w,
                     Bv.z, Bv.w);
            if (full) {
                out[rbase[mt][0] + v0]     = acc[0] - lse[mt][0];
                out[rbase[mt][0] + v0 + 1] = acc[1] - lse[mt][0];
                out[rbase[mt][1] + v0]     = acc[2] - lse[mt][1];
                out[rbase[mt][1] + v0 + 1] = acc[3] - lse[mt][1];
            } else {
                if (v0 < VV)     { out[rbase[mt][0] + v0]     = acc[0] - lse[mt][0];
                                   out[rbase[mt][1] + v0]     = acc[2] - lse[mt][1]; }
                if (v0 + 1 < VV) { out[rbase[mt][0] + v0 + 1] = acc[1] - lse[mt][0];
                                   out[rbase[mt][1] + v0 + 1] = acc[3] - lse[mt][1]; }
            }
        }
    }
}

// ---------------------------------------------------------------------------
extern "C" void kernel_launch(void* const* d_in, const int* in_sizes, int n_in,
                              void* d_out, int out_size) {
    const int*   idx = (const int*)  d_in[0];
    const float* emb = (const float*)d_in[1];
    const float* Wf  = (const float*)d_in[2];
    const float* bf  = (const float*)d_in[3];
    const float* Wi  = (const float*)d_in[4];
    const float* bi  = (const float*)d_in[5];
    const float* Wc  = (const float*)d_in[6];
    const float* bc  = (const float*)d_in[7];
    const float* Wo  = (const float*)d_in[8];
    const float* bo  = (const float*)d_in[9];
    const float* Who = (const float*)d_in[10];
    const float* bho = (const float*)d_in[11];
    const float* h0  = (const float*)d_in[12];
    const float* C0  = (const float*)d_in[13];
    float* out = (float*)d_out;

    k_prep<<<PREP_BLKS + PRE_BLKS, 256>>>(Who, bho, idx, emb,
                                          Wf, bf, Wi, bi, Wc, bc, Wo, bo);
    k_recur<<<64, 32>>>(Wf, Wi, Wc, Wo, h0, C0);

    dim3 grid(VPAD / N_BLK, SB / M_BLK);   // 393 x 16
    k_sumexp<<<grid, 256>>>(0);
    k_write<<<grid, 256>>>(out);
}